// round 1
// baseline (speedup 1.0000x reference)
#include <cuda_runtime.h>
#include <math_constants.h>
#include <cstdint>

#define NC  81
#define BK  10
#define DIM 2048
#define NI  16384

__device__ float g_mmean[NC * DIM];
__device__ float g_bias[NC];
__device__ int   g_count;

// ---------------------------------------------------------------------------
// Kernel 1: per-class bank mean + 0.5*|mean|^2 bias; also zero the acc counter
// ---------------------------------------------------------------------------
__global__ void k_mean(const float* __restrict__ mem) {
    int c = blockIdx.x;
    int tid = threadIdx.x;
    if (c == 0 && tid == 0) g_count = 0;
    float part = 0.f;
    for (int d = tid; d < DIM; d += 256) {
        float s = 0.f;
#pragma unroll
        for (int b = 0; b < BK; b++) s += mem[(size_t)(c * BK + b) * DIM + d];
        float m = s * (1.0f / BK);
        g_mmean[c * DIM + d] = m;
        part += m * m;
    }
#pragma unroll
    for (int o = 16; o; o >>= 1) part += __shfl_xor_sync(0xffffffffu, part, o);
    __shared__ float rb[8];
    if ((tid & 31) == 0) rb[tid >> 5] = part;
    __syncthreads();
    if (tid == 0) {
        float t = 0.f;
#pragma unroll
        for (int w = 0; w < 8; w++) t += rb[w];
        g_bias[c] = 0.5f * t;
    }
}

// ---------------------------------------------------------------------------
// Kernel 2: tiled fp32 GEMM (scores = bias - x.mean) + per-instance argmin.
// Block: 64 instances x all 81 classes. 256 threads: thread = (iG 0..15, cG 0..15),
// register tile 4 instances x 6 classes.
// ---------------------------------------------------------------------------
__global__ void __launch_bounds__(256) k_gemm(const float* __restrict__ X,
                                              const int* __restrict__ labels,
                                              float* __restrict__ out) {
    __shared__ float xs[64][33];
    __shared__ float ms[96][33];
    __shared__ float sc[64][96];

    int tid = threadIdx.x;
    int iG = tid & 15;
    int cG = tid >> 4;
    int i0 = blockIdx.x * 64;

    float acc[4][6];
#pragma unroll
    for (int m = 0; m < 4; m++)
#pragma unroll
        for (int j = 0; j < 6; j++) acc[m][j] = 0.f;

    int r = tid >> 5;      // 0..7
    int kk = tid & 31;     // 0..31

    for (int k0 = 0; k0 < DIM; k0 += 32) {
#pragma unroll
        for (int rr = 0; rr < 8; rr++) {
            int row = r + rr * 8;
            xs[row][kk] = X[(size_t)(i0 + row) * DIM + k0 + kk];
        }
#pragma unroll
        for (int rr = 0; rr < 12; rr++) {
            int row = r + rr * 8;
            ms[row][kk] = (row < NC) ? g_mmean[row * DIM + k0 + kk] : 0.f;
        }
        __syncthreads();
#pragma unroll
        for (int k = 0; k < 32; k++) {
            float xv[4], mv[6];
#pragma unroll
            for (int m = 0; m < 4; m++) xv[m] = xs[iG * 4 + m][k];
#pragma unroll
            for (int j = 0; j < 6; j++) mv[j] = ms[cG * 6 + j][k];
#pragma unroll
            for (int m = 0; m < 4; m++)
#pragma unroll
                for (int j = 0; j < 6; j++) acc[m][j] += xv[m] * mv[j];
        }
        __syncthreads();
    }

    // write scores (only classes < 81 are read)
#pragma unroll
    for (int j = 0; j < 6; j++) {
        int c = cG * 6 + j;
        if (c < NC) {
            float b = g_bias[c];
#pragma unroll
            for (int m = 0; m < 4; m++) sc[iG * 4 + m][c] = b - acc[m][j];
        }
    }
    __syncthreads();

    if (tid < 64) {
        int gi = i0 + tid;
        float best = sc[tid][0];
        int bc = 0;
#pragma unroll 4
        for (int c = 1; c < NC; c++) {
            float v = sc[tid][c];
            if (v < best) { best = v; bc = c; }
        }
        out[gi] = (float)bc;
        int correct = (bc == labels[gi]) ? 1 : 0;
        unsigned bal = __ballot_sync(0xffffffffu, correct != 0);
        if ((tid & 31) == 0) atomicAdd(&g_count, __popc(bal));
    }
}

// ---------------------------------------------------------------------------
// Kernel 3: finalize accuracy
// ---------------------------------------------------------------------------
__global__ void k_fin(float* __restrict__ out) {
    out[NI] = (float)g_count * (1.0f / NI);
}

// ---------------------------------------------------------------------------
// Kernel 4: sequential per-class memory update. One block per class.
// Bank kept in registers (thread t owns dims [4t,4t+4) and [1024+4t, +4)).
// ||b_j - x||^2 = bn[j] - 2 b_j.x + |x|^2 with bn maintained incrementally.
// ---------------------------------------------------------------------------
__global__ void __launch_bounds__(256, 1) k_update(const float* __restrict__ X,
                                                   const int* __restrict__ labels,
                                                   const float* __restrict__ mem,
                                                   const int* __restrict__ mpos,
                                                   float* __restrict__ out) {
    const int c = blockIdx.x;
    const int tid = threadIdx.x;
    const int w = tid >> 5;
    const int lane = tid & 31;

    __shared__ int   s_list[1024];
    __shared__ int   s_cnt;
    __shared__ int   s_wcnt[8];
    __shared__ float s_part[11 * 8];
    __shared__ float s_red[11];
    __shared__ float s_bn[BK];

    // ---- build ordered index list for class c (8 warps, contiguous segments) ----
    const int SEG = NI / 8;  // 2048, = 16 int4-chunks of 128 per warp
    const int base = w * SEG;
    const int4* lab4 = (const int4*)labels;

    int cnt = 0;
    for (int it = 0; it < SEG / 128; it++) {
        int4 v = lab4[(base >> 2) + it * 32 + lane];
        cnt += (v.x == c) + (v.y == c) + (v.z == c) + (v.w == c);
    }
#pragma unroll
    for (int o = 16; o; o >>= 1) cnt += __shfl_xor_sync(0xffffffffu, cnt, o);
    if (lane == 0) s_wcnt[w] = cnt;
    __syncthreads();
    if (tid == 0) {
        int t = 0;
        for (int ww = 0; ww < 8; ww++) { int v = s_wcnt[ww]; s_wcnt[ww] = t; t += v; }
        s_cnt = t;
    }
    __syncthreads();
    int off = s_wcnt[w];
    for (int it = 0; it < SEG / 128; it++) {
        int gidx = base + it * 128 + lane * 4;
        int4 v = lab4[gidx >> 2];
        int m0 = (v.x == c), m1 = (v.y == c), m2 = (v.z == c), m3 = (v.w == c);
        int nm = m0 + m1 + m2 + m3;
        int x = nm;
#pragma unroll
        for (int o = 1; o < 32; o <<= 1) {
            int y = __shfl_up_sync(0xffffffffu, x, o);
            if (lane >= o) x += y;
        }
        int p = off + x - nm;
        if (m0) { s_list[p < 1024 ? p : 1023] = gidx + 0; p++; }
        if (m1) { s_list[p < 1024 ? p : 1023] = gidx + 1; p++; }
        if (m2) { s_list[p < 1024 ? p : 1023] = gidx + 2; p++; }
        if (m3) { s_list[p < 1024 ? p : 1023] = gidx + 3; p++; }
        off += __shfl_sync(0xffffffffu, x, 31);
    }
    __syncthreads();

    // ---- load bank into registers; compute |b_j|^2 ----
    const float4* mem4 = (const float4*)mem + (size_t)c * BK * (DIM / 4);
    float4 br[BK][2];
    float part[11];
#pragma unroll
    for (int j = 0; j < BK; j++) {
        br[j][0] = mem4[j * (DIM / 4) + tid];
        br[j][1] = mem4[j * (DIM / 4) + 256 + tid];
        float4 a = br[j][0], b = br[j][1];
        part[j] = a.x * a.x + a.y * a.y + a.z * a.z + a.w * a.w +
                  b.x * b.x + b.y * b.y + b.z * b.z + b.w * b.w;
    }
#pragma unroll
    for (int j = 0; j < BK; j++) {
        float v = part[j];
#pragma unroll
        for (int o = 16; o; o >>= 1) v += __shfl_xor_sync(0xffffffffu, v, o);
        if (lane == 0) s_part[j * 8 + w] = v;
    }
    __syncthreads();
    if (tid < BK) {
        float t = 0.f;
#pragma unroll
        for (int ww = 0; ww < 8; ww++) t += s_part[tid * 8 + ww];
        s_bn[tid] = t;
    }
    __syncthreads();

    // ---- sequential scan over this class's instances ----
    int p = mpos[c];
    const int n = s_cnt;
    const float4* X4 = (const float4*)X;
    float4 xc0 = {0, 0, 0, 0}, xc1 = {0, 0, 0, 0};
    float4 xn0 = {0, 0, 0, 0}, xn1 = {0, 0, 0, 0};
    if (n > 0) {
        size_t rr = (size_t)s_list[0] * (DIM / 4);
        xc0 = X4[rr + tid];
        xc1 = X4[rr + 256 + tid];
    }

    for (int s = 0; s < n; s++) {
        if (s + 1 < n) {
            size_t rr = (size_t)s_list[s + 1] * (DIM / 4);
            xn0 = X4[rr + tid];
            xn1 = X4[rr + 256 + tid];
        }
        // per-thread partial dots b_j.x and |x|^2
#pragma unroll
        for (int j = 0; j < BK; j++) {
            float4 a = br[j][0], b = br[j][1];
            part[j] = a.x * xc0.x + a.y * xc0.y + a.z * xc0.z + a.w * xc0.w +
                      b.x * xc1.x + b.y * xc1.y + b.z * xc1.z + b.w * xc1.w;
        }
        part[10] = xc0.x * xc0.x + xc0.y * xc0.y + xc0.z * xc0.z + xc0.w * xc0.w +
                   xc1.x * xc1.x + xc1.y * xc1.y + xc1.z * xc1.z + xc1.w * xc1.w;
#pragma unroll
        for (int j = 0; j < 11; j++) {
            float v = part[j];
#pragma unroll
            for (int o = 16; o; o >>= 1) v += __shfl_xor_sync(0xffffffffu, v, o);
            if (lane == 0) s_part[j * 8 + w] = v;
        }
        __syncthreads();
        if (tid < 11) {
            float t = 0.f;
#pragma unroll
            for (int ww = 0; ww < 8; ww++) t += s_part[tid * 8 + ww];
            s_red[tid] = t;
        }
        __syncthreads();

        int slot;
        if (p < BK) {
            slot = p;
        } else {
            // argmax_j ||b_j - x||^2, first-max tie-break (strict >)
            float xx = s_red[10];
            float best = -CUDART_INF_F;
            int bi = 0;
#pragma unroll
            for (int j = 0; j < BK; j++) {
                float d2 = s_bn[j] - 2.f * s_red[j] + xx;
                if (d2 > best) { best = d2; bi = j; }
            }
            slot = bi;
        }
        __syncthreads();  // everyone done reading s_bn/s_red before the update
        if (tid == 0) s_bn[slot] = s_red[10];
#pragma unroll
        for (int j = 0; j < BK; j++) {
            if (j == slot) { br[j][0] = xc0; br[j][1] = xc1; }
        }
        if (p < BK) p++;
        xc0 = xn0;
        xc1 = xn1;
    }

    // ---- epilogue: write updated bank + pos (out+16385 is only 4B aligned) ----
    float* out_mem = out + (NI + 1) + (size_t)c * BK * DIM;
#pragma unroll
    for (int j = 0; j < BK; j++) {
        float4 a = br[j][0], b = br[j][1];
        int d0 = j * DIM + tid * 4;
        out_mem[d0 + 0] = a.x; out_mem[d0 + 1] = a.y;
        out_mem[d0 + 2] = a.z; out_mem[d0 + 3] = a.w;
        int d1 = j * DIM + 1024 + tid * 4;
        out_mem[d1 + 0] = b.x; out_mem[d1 + 1] = b.y;
        out_mem[d1 + 2] = b.z; out_mem[d1 + 3] = b.w;
    }
    if (tid == 0) out[(NI + 1) + (size_t)NC * BK * DIM + c] = (float)p;
}

// ---------------------------------------------------------------------------
extern "C" void kernel_launch(void* const* d_in, const int* in_sizes, int n_in,
                              void* d_out, int out_size) {
    const float* X      = (const float*)d_in[0];
    const int*   labels = (const int*)d_in[1];
    const float* mem    = (const float*)d_in[2];
    const int*   mpos   = (const int*)d_in[3];
    float* out = (float*)d_out;

    k_mean<<<NC, 256>>>(mem);
    k_gemm<<<NI / 64, 256>>>(X, labels, out);
    k_fin<<<1, 1>>>(out);
    k_update<<<NC, 256>>>(X, labels, mem, mpos, out);
}